// round 2
// baseline (speedup 1.0000x reference)
#include <cuda_runtime.h>
#include <math.h>

// Problem constants
#define Bb 8
#define Ss 4096
#define Dd 1024
#define Rr 256
#define Mtot (Bb*Ss)      // 32768
#define CHUNKS 64
#define CLEN 64           // Ss / CHUNKS

// Scratch (static __device__ — no allocations allowed)
__device__ float g_fnorm[Rr*Dd];            // normalized frequencies
__device__ float g_invnorm[Mtot];           // 1/max(||x_row||, eps)
__device__ float g_xm_part[Bb*32*Dd];       // partial sums for mean
__device__ float g_xm[Bb*Dd];               // sum over S (scaled later)
__device__ float g_gate[Bb*Rr];
__device__ float g_ret[Bb*Rr];
__device__ float g_sig[(size_t)Mtot*Rr];    // signal -> accumulated (in place)
__device__ float g_carrySum[Bb*CHUNKS*Rr];
__device__ float g_carryIn[Bb*CHUNKS*Rr];

// ---------------------------------------------------------------------------
// f_norm: one block per row of frequencies (256 x 1024)
__global__ void fnorm_kernel(const float* __restrict__ freq) {
    int r = blockIdx.x;
    int tid = threadIdx.x;
    const float4* row = (const float4*)(freq + (size_t)r*Dd);
    float4 v = row[tid];
    float s = v.x*v.x + v.y*v.y + v.z*v.z + v.w*v.w;
    #pragma unroll
    for (int o = 16; o; o >>= 1) s += __shfl_xor_sync(0xffffffffu, s, o);
    __shared__ float ws[8];
    __shared__ float invs;
    int w = tid >> 5, l = tid & 31;
    if (l == 0) ws[w] = s;
    __syncthreads();
    if (tid == 0) {
        float t = 0.f;
        #pragma unroll
        for (int i = 0; i < 8; i++) t += ws[i];
        invs = 1.0f / fmaxf(sqrtf(t), 1e-12f);
    }
    __syncthreads();
    float iv = invs;
    ((float4*)g_fnorm)[(size_t)r*(Dd/4) + tid] =
        make_float4(v.x*iv, v.y*iv, v.z*iv, v.w*iv);
}

// inv row-norm of x: one block per (b,s) row
__global__ void invnorm_kernel(const float* __restrict__ x) {
    int m = blockIdx.x;
    int tid = threadIdx.x;
    const float4* row = (const float4*)(x + (size_t)m*Dd);
    float4 v = row[tid];
    float s = v.x*v.x + v.y*v.y + v.z*v.z + v.w*v.w;
    #pragma unroll
    for (int o = 16; o; o >>= 1) s += __shfl_xor_sync(0xffffffffu, s, o);
    __shared__ float ws[8];
    int w = tid >> 5, l = tid & 31;
    if (l == 0) ws[w] = s;
    __syncthreads();
    if (tid == 0) {
        float t = 0.f;
        #pragma unroll
        for (int i = 0; i < 8; i++) t += ws[i];
        g_invnorm[m] = 1.0f / fmaxf(sqrtf(t), 1e-12f);
    }
}

// xm partial sums: grid (32 chunks, B). Each block sums 128 s-rows.
__global__ void xm_part_kernel(const float* __restrict__ x) {
    int c = blockIdx.x;
    int b = blockIdx.y;
    int tid = threadIdx.x;
    #pragma unroll
    for (int q = 0; q < 4; q++) {
        int d = q*256 + tid;
        const float* p = x + ((size_t)(b*Ss + c*128))*Dd + d;
        float s = 0.f;
        #pragma unroll 4
        for (int t = 0; t < 128; t++) s += p[(size_t)t*Dd];
        g_xm_part[(size_t)(b*32 + c)*Dd + d] = s;
    }
}

__global__ void xm_reduce_kernel() {
    int b = blockIdx.x;
    int d = threadIdx.x;   // 1024 threads
    float s = 0.f;
    #pragma unroll
    for (int c = 0; c < 32; c++) s += g_xm_part[(size_t)(b*32 + c)*Dd + d];
    g_xm[(size_t)b*Dd + d] = s;   // raw sum; /4096 applied in gates kernel
}

// gate + retention: one warp per (b,r)
__global__ void gates_kernel(const float* __restrict__ gate_w,
                             const float* __restrict__ gate_bias,
                             const float* __restrict__ ret_w,
                             const float* __restrict__ ret_bias) {
    int gw = (blockIdx.x*blockDim.x + threadIdx.x) >> 5;  // 0..2047
    int lane = threadIdx.x & 31;
    int b = gw >> 8;
    int r = gw & 255;
    const float4* xm4 = (const float4*)(g_xm + (size_t)b*Dd);
    const float4* gw4 = (const float4*)(gate_w + (size_t)r*Dd);
    const float4* rw4 = (const float4*)(ret_w + (size_t)r*Dd);
    float dg = 0.f, dr = 0.f;
    #pragma unroll
    for (int i = 0; i < 8; i++) {
        int k = i*32 + lane;
        float4 xv = xm4[k], gv = gw4[k], rv = rw4[k];
        dg += xv.x*gv.x + xv.y*gv.y + xv.z*gv.z + xv.w*gv.w;
        dr += xv.x*rv.x + xv.y*rv.y + xv.z*rv.z + xv.w*rv.w;
    }
    #pragma unroll
    for (int o = 16; o; o >>= 1) {
        dg += __shfl_xor_sync(0xffffffffu, dg, o);
        dr += __shfl_xor_sync(0xffffffffu, dr, o);
    }
    if (lane == 0) {
        const float sc = 1.0f/4096.0f;
        float gl = dg*sc + gate_bias[r];
        float gs = 1.0f/(1.0f + expf(-gl));
        g_gate[b*Rr + r] = (gs >= 0.001f) ? gs : 0.0f;
        float rl = dr*sc + ret_bias[r];
        g_ret[b*Rr + r] = 1.0f/(1.0f + expf(-rl));
    }
}

// ---------------------------------------------------------------------------
// GEMM1: signal[m, r] = (x[m,:] . f_norm[r,:]) * invnorm[m] * gate[b, r]
// 128x128x8 tile, 256 threads, 8x8 per-thread microtile.
__global__ void __launch_bounds__(256) gemm1_kernel(const float* __restrict__ x) {
    __shared__ float As[8][128];
    __shared__ float Bs[8][128];
    const int K = Dd;
    int tid = threadIdx.x;
    int tx = tid & 15, ty = tid >> 4;
    int bn = blockIdx.x, bm = blockIdx.y;
    int lRow = tid >> 1;
    int lCol = (tid & 1) << 2;
    const float* Ap = x       + (size_t)(bm*128 + lRow)*K + lCol;
    const float* Bp = g_fnorm + (size_t)(bn*128 + lRow)*K + lCol;
    float acc[8][8];
    #pragma unroll
    for (int i = 0; i < 8; i++)
        #pragma unroll
        for (int j = 0; j < 8; j++) acc[i][j] = 0.f;

    float4 av = *(const float4*)Ap;
    float4 bv = *(const float4*)Bp;
    for (int k0 = 0; k0 < K; k0 += 8) {
        As[lCol+0][lRow] = av.x; As[lCol+1][lRow] = av.y;
        As[lCol+2][lRow] = av.z; As[lCol+3][lRow] = av.w;
        Bs[lCol+0][lRow] = bv.x; Bs[lCol+1][lRow] = bv.y;
        Bs[lCol+2][lRow] = bv.z; Bs[lCol+3][lRow] = bv.w;
        __syncthreads();
        if (k0 + 8 < K) {
            av = *(const float4*)(Ap + k0 + 8);
            bv = *(const float4*)(Bp + k0 + 8);
        }
        #pragma unroll
        for (int kk = 0; kk < 8; kk++) {
            float a0[8], b0[8];
            *(float4*)&a0[0] = *(const float4*)&As[kk][ty*8];
            *(float4*)&a0[4] = *(const float4*)&As[kk][ty*8 + 4];
            *(float4*)&b0[0] = *(const float4*)&Bs[kk][tx*8];
            *(float4*)&b0[4] = *(const float4*)&Bs[kk][tx*8 + 4];
            #pragma unroll
            for (int i = 0; i < 8; i++)
                #pragma unroll
                for (int j = 0; j < 8; j++)
                    acc[i][j] = fmaf(a0[i], b0[j], acc[i][j]);
        }
        __syncthreads();
    }
    int mBase = bm*128 + ty*8;
    int nBase = bn*128 + tx*8;
    int b = bm >> 5;                 // 32 M-blocks per batch, so constant per block
    float gr[8];
    #pragma unroll
    for (int j = 0; j < 8; j++) gr[j] = g_gate[b*Rr + nBase + j];
    #pragma unroll
    for (int i = 0; i < 8; i++) {
        float inv = g_invnorm[mBase + i];
        float o[8];
        #pragma unroll
        for (int j = 0; j < 8; j++) o[j] = acc[i][j] * inv * gr[j];
        float* orow = g_sig + (size_t)(mBase + i)*Rr + nBase;
        *(float4*)&orow[0] = *(float4*)&o[0];
        *(float4*)&orow[4] = *(float4*)&o[4];
    }
}

// GEMM2: out[m, d] = acc[m,:] . out_w[d,:]  (K = 256)
__global__ void __launch_bounds__(256) gemm2_kernel(const float* __restrict__ outw,
                                                    float* __restrict__ out) {
    __shared__ float As[8][128];
    __shared__ float Bs[8][128];
    const int K = Rr;
    int tid = threadIdx.x;
    int tx = tid & 15, ty = tid >> 4;
    int bn = blockIdx.x, bm = blockIdx.y;
    int lRow = tid >> 1;
    int lCol = (tid & 1) << 2;
    const float* Ap = g_sig + (size_t)(bm*128 + lRow)*K + lCol;
    const float* Bp = outw  + (size_t)(bn*128 + lRow)*K + lCol;
    float acc[8][8];
    #pragma unroll
    for (int i = 0; i < 8; i++)
        #pragma unroll
        for (int j = 0; j < 8; j++) acc[i][j] = 0.f;

    float4 av = *(const float4*)Ap;
    float4 bv = *(const float4*)Bp;
    for (int k0 = 0; k0 < K; k0 += 8) {
        As[lCol+0][lRow] = av.x; As[lCol+1][lRow] = av.y;
        As[lCol+2][lRow] = av.z; As[lCol+3][lRow] = av.w;
        Bs[lCol+0][lRow] = bv.x; Bs[lCol+1][lRow] = bv.y;
        Bs[lCol+2][lRow] = bv.z; Bs[lCol+3][lRow] = bv.w;
        __syncthreads();
        if (k0 + 8 < K) {
            av = *(const float4*)(Ap + k0 + 8);
            bv = *(const float4*)(Bp + k0 + 8);
        }
        #pragma unroll
        for (int kk = 0; kk < 8; kk++) {
            float a0[8], b0[8];
            *(float4*)&a0[0] = *(const float4*)&As[kk][ty*8];
            *(float4*)&a0[4] = *(const float4*)&As[kk][ty*8 + 4];
            *(float4*)&b0[0] = *(const float4*)&Bs[kk][tx*8];
            *(float4*)&b0[4] = *(const float4*)&Bs[kk][tx*8 + 4];
            #pragma unroll
            for (int i = 0; i < 8; i++)
                #pragma unroll
                for (int j = 0; j < 8; j++)
                    acc[i][j] = fmaf(a0[i], b0[j], acc[i][j]);
        }
        __syncthreads();
    }
    int mBase = bm*128 + ty*8;
    int nBase = bn*128 + tx*8;
    #pragma unroll
    for (int i = 0; i < 8; i++) {
        float* orow = out + (size_t)(mBase + i)*Dd + nBase;
        *(float4*)&orow[0] = *(float4*)&acc[i][0];
        *(float4*)&orow[4] = *(float4*)&acc[i][4];
    }
}

// ---------------------------------------------------------------------------
// Scan stage A: chunk-local scans with zero carry-in (in place), record sums.
__global__ void scanA_kernel() {
    int c = blockIdx.x, b = blockIdx.y;
    int r = threadIdx.x;
    float ret = g_ret[b*Rr + r];
    float* base = g_sig + ((size_t)(b*Ss + c*CLEN))*Rr + r;
    float a = 0.f;
    #pragma unroll 8
    for (int t = 0; t < CLEN; t++) {
        float s = base[(size_t)t*Rr];
        a = fmaf(a, ret, s);
        base[(size_t)t*Rr] = a;
    }
    g_carrySum[(size_t)(b*CHUNKS + c)*Rr + r] = a;
}

// Scan stage B: sequential carry across chunks; also emits final_state.
__global__ void scanB_kernel(const float* __restrict__ prev,
                             float* __restrict__ final_state) {
    int b = blockIdx.x;
    int r = threadIdx.x;
    float ret = g_ret[b*Rr + r];
    float p = ret;
    #pragma unroll
    for (int i = 0; i < 6; i++) p *= p;   // ret^64
    float carry = prev[b*Rr + r];          // a_{-1}
    #pragma unroll 4
    for (int c = 0; c < CHUNKS; c++) {
        g_carryIn[(size_t)(b*CHUNKS + c)*Rr + r] = carry;
        carry = fmaf(carry, p, g_carrySum[(size_t)(b*CHUNKS + c)*Rr + r]);
    }
    final_state[b*Rr + r] = carry;
}

// Scan stage C: add carry * ret^(t+1) to each chunk-local value.
__global__ void scanC_kernel() {
    int c = blockIdx.x, b = blockIdx.y;
    int r = threadIdx.x;
    float ret = g_ret[b*Rr + r];
    float cin = g_carryIn[(size_t)(b*CHUNKS + c)*Rr + r];
    float m = ret;
    float* base = g_sig + ((size_t)(b*Ss + c*CLEN))*Rr + r;
    #pragma unroll 8
    for (int t = 0; t < CLEN; t++) {
        base[(size_t)t*Rr] = fmaf(cin, m, base[(size_t)t*Rr]);
        m *= ret;
    }
}

// ---------------------------------------------------------------------------
extern "C" void kernel_launch(void* const* d_in, const int* in_sizes, int n_in,
                              void* d_out, int out_size) {
    const float* x     = (const float*)d_in[0];
    const float* prev  = (const float*)d_in[1];
    const float* freq  = (const float*)d_in[2];
    const float* rbias = (const float*)d_in[3];
    const float* rw    = (const float*)d_in[4];
    const float* gw    = (const float*)d_in[5];
    const float* gbias = (const float*)d_in[6];
    const float* outw  = (const float*)d_in[7];
    float* out = (float*)d_out;
    float* final_state = out + (size_t)Mtot*Dd;

    fnorm_kernel<<<Rr, 256>>>(freq);
    invnorm_kernel<<<Mtot, 256>>>(x);
    xm_part_kernel<<<dim3(32, Bb), 256>>>(x);
    xm_reduce_kernel<<<Bb, 1024>>>();
    gates_kernel<<<256, 256>>>(gw, gbias, rw, rbias);
    gemm1_kernel<<<dim3(Rr/128, Mtot/128), 256>>>(x);
    scanA_kernel<<<dim3(CHUNKS, Bb), 256>>>();
    scanB_kernel<<<Bb, Rr>>>(prev, final_state);
    scanC_kernel<<<dim3(CHUNKS, Bb), 256>>>();
    gemm2_kernel<<<dim3(Dd/128, Mtot/128), 256>>>(outw, out);
}

// round 5
// speedup vs baseline: 2.1237x; 2.1237x over previous
#include <cuda_runtime.h>
#include <cuda_bf16.h>
#include <math.h>
#include <stdint.h>

// Problem constants
#define Bb 8
#define Ss 4096
#define Dd 1024
#define Rr 256
#define Mtot (Bb*Ss)      // 32768
#define CHUNKS 64
#define CLEN 64

// ---------------------------------------------------------------------------
// Static device scratch
__device__ __nv_bfloat16 g_x_hi[(size_t)Mtot*Dd];     // xhat = x/||x|| hi
__device__ __nv_bfloat16 g_x_lo[(size_t)Mtot*Dd];     // xhat lo
__device__ __nv_bfloat16 g_fnorm_hi[Rr*Dd];
__device__ __nv_bfloat16 g_fnorm_lo[Rr*Dd];
__device__ __nv_bfloat16 g_outw_hi[Dd*Rr];
__device__ __nv_bfloat16 g_outw_lo[Dd*Rr];
__device__ __nv_bfloat16 g_acc_hi[(size_t)Mtot*Rr];   // accumulated hi
__device__ __nv_bfloat16 g_acc_lo[(size_t)Mtot*Rr];   // accumulated lo
__device__ float g_xm_part[Bb*32*Dd];
__device__ float g_xm[Bb*Dd];
__device__ float g_gate[Bb*Rr];
__device__ float g_ret[Bb*Rr];
__device__ float g_sig[(size_t)Mtot*Rr];
__device__ float g_carrySum[Bb*CHUNKS*Rr];
__device__ float g_carryIn[Bb*CHUNKS*Rr];

// ---------------------------------------------------------------------------
// PTX helpers (all sm_100-plain legal: cp.async / ldmatrix / mma.sync)
__device__ __forceinline__ uint32_t smem_u32(const void* p) {
    uint32_t a;
    asm("{ .reg .u64 t; cvta.to.shared.u64 t, %1; cvt.u32.u64 %0, t; }" : "=r"(a) : "l"(p));
    return a;
}
#define CP16(dst, src)  asm volatile("cp.async.cg.shared.global [%0], [%1], 16;" :: "r"(dst), "l"(src) : "memory")
#define CP_COMMIT()     asm volatile("cp.async.commit_group;" ::: "memory")
#define CP_WAIT1()      asm volatile("cp.async.wait_group 1;" ::: "memory")

__device__ __forceinline__ void ldsm4(uint32_t* r, uint32_t addr) {
    asm volatile("ldmatrix.sync.aligned.m8n8.x4.shared.b16 {%0,%1,%2,%3}, [%4];"
        : "=r"(r[0]), "=r"(r[1]), "=r"(r[2]), "=r"(r[3]) : "r"(addr));
}
__device__ __forceinline__ void mma16816(float* c, const uint32_t* a, const uint32_t* b) {
    asm volatile("mma.sync.aligned.m16n8k16.row.col.f32.bf16.bf16.f32 "
        "{%0,%1,%2,%3}, {%4,%5,%6,%7}, {%8,%9}, {%0,%1,%2,%3};"
        : "+f"(c[0]), "+f"(c[1]), "+f"(c[2]), "+f"(c[3])
        : "r"(a[0]), "r"(a[1]), "r"(a[2]), "r"(a[3]), "r"(b[0]), "r"(b[1]));
}
#define SWZ(o) ((o) ^ (((o) >> 3) & 0x70))

// bf16 hi/lo split
__device__ __forceinline__ void split1(float v, unsigned short& h, unsigned short& l) {
    __nv_bfloat16 hb = __float2bfloat16_rn(v);
    float r = v - __bfloat162float(hb);
    __nv_bfloat16 lb = __float2bfloat16_rn(r);
    h = *reinterpret_cast<unsigned short*>(&hb);
    l = *reinterpret_cast<unsigned short*>(&lb);
}
__device__ __forceinline__ void split4(float4 v, unsigned long long& hv, unsigned long long& lv) {
    unsigned short h0,h1,h2,h3,l0,l1,l2,l3;
    split1(v.x,h0,l0); split1(v.y,h1,l1); split1(v.z,h2,l2); split1(v.w,h3,l3);
    hv = (unsigned long long)h0 | ((unsigned long long)h1<<16) |
         ((unsigned long long)h2<<32) | ((unsigned long long)h3<<48);
    lv = (unsigned long long)l0 | ((unsigned long long)l1<<16) |
         ((unsigned long long)l2<<32) | ((unsigned long long)l3<<48);
}

// ---------------------------------------------------------------------------
// xhat: per-row normalize x and split to bf16 hi/lo. One block per row.
__global__ void xhat_kernel(const float* __restrict__ x) {
    int m = blockIdx.x;
    int tid = threadIdx.x;
    float4 v = ((const float4*)(x + (size_t)m*Dd))[tid];
    float s = v.x*v.x + v.y*v.y + v.z*v.z + v.w*v.w;
    #pragma unroll
    for (int o = 16; o; o >>= 1) s += __shfl_xor_sync(0xffffffffu, s, o);
    __shared__ float ws[8];
    __shared__ float invs;
    int w = tid >> 5, l = tid & 31;
    if (l == 0) ws[w] = s;
    __syncthreads();
    if (tid == 0) {
        float t = 0.f;
        #pragma unroll
        for (int i = 0; i < 8; i++) t += ws[i];
        invs = 1.0f / fmaxf(sqrtf(t), 1e-12f);
    }
    __syncthreads();
    float iv = invs;
    float4 n = make_float4(v.x*iv, v.y*iv, v.z*iv, v.w*iv);
    unsigned long long hv, lv;
    split4(n, hv, lv);
    *(unsigned long long*)(g_x_hi + (size_t)m*Dd + tid*4) = hv;
    *(unsigned long long*)(g_x_lo + (size_t)m*Dd + tid*4) = lv;
}

// f_norm split
__global__ void fnorm_kernel(const float* __restrict__ freq) {
    int r = blockIdx.x;
    int tid = threadIdx.x;
    float4 v = ((const float4*)(freq + (size_t)r*Dd))[tid];
    float s = v.x*v.x + v.y*v.y + v.z*v.z + v.w*v.w;
    #pragma unroll
    for (int o = 16; o; o >>= 1) s += __shfl_xor_sync(0xffffffffu, s, o);
    __shared__ float ws[8];
    __shared__ float invs;
    int w = tid >> 5, l = tid & 31;
    if (l == 0) ws[w] = s;
    __syncthreads();
    if (tid == 0) {
        float t = 0.f;
        #pragma unroll
        for (int i = 0; i < 8; i++) t += ws[i];
        invs = 1.0f / fmaxf(sqrtf(t), 1e-12f);
    }
    __syncthreads();
    float iv = invs;
    float4 n = make_float4(v.x*iv, v.y*iv, v.z*iv, v.w*iv);
    unsigned long long hv, lv;
    split4(n, hv, lv);
    *(unsigned long long*)(g_fnorm_hi + (size_t)r*Dd + tid*4) = hv;
    *(unsigned long long*)(g_fnorm_lo + (size_t)r*Dd + tid*4) = lv;
}

__global__ void outw_split_kernel(const float* __restrict__ w) {
    int idx = (blockIdx.x*256 + threadIdx.x)*4;
    float4 v = *(const float4*)(w + idx);
    unsigned long long hv, lv;
    split4(v, hv, lv);
    *(unsigned long long*)(g_outw_hi + idx) = hv;
    *(unsigned long long*)(g_outw_lo + idx) = lv;
}

// xm + gates
__global__ void xm_part_kernel(const float* __restrict__ x) {
    int c = blockIdx.x, b = blockIdx.y;
    int tid = threadIdx.x;
    #pragma unroll
    for (int q = 0; q < 4; q++) {
        int d = q*256 + tid;
        const float* p = x + ((size_t)(b*Ss + c*128))*Dd + d;
        float s = 0.f;
        #pragma unroll 4
        for (int t = 0; t < 128; t++) s += p[(size_t)t*Dd];
        g_xm_part[(size_t)(b*32 + c)*Dd + d] = s;
    }
}
__global__ void xm_reduce_kernel() {
    int b = blockIdx.x, d = threadIdx.x;
    float s = 0.f;
    #pragma unroll
    for (int c = 0; c < 32; c++) s += g_xm_part[(size_t)(b*32 + c)*Dd + d];
    g_xm[(size_t)b*Dd + d] = s;
}
__global__ void gates_kernel(const float* __restrict__ gate_w,
                             const float* __restrict__ gate_bias,
                             const float* __restrict__ ret_w,
                             const float* __restrict__ ret_bias) {
    int gw = (blockIdx.x*blockDim.x + threadIdx.x) >> 5;
    int lane = threadIdx.x & 31;
    int b = gw >> 8, r = gw & 255;
    const float4* xm4 = (const float4*)(g_xm + (size_t)b*Dd);
    const float4* gw4 = (const float4*)(gate_w + (size_t)r*Dd);
    const float4* rw4 = (const float4*)(ret_w + (size_t)r*Dd);
    float dg = 0.f, dr = 0.f;
    #pragma unroll
    for (int i = 0; i < 8; i++) {
        int k = i*32 + lane;
        float4 xv = xm4[k], gv = gw4[k], rv = rw4[k];
        dg += xv.x*gv.x + xv.y*gv.y + xv.z*gv.z + xv.w*gv.w;
        dr += xv.x*rv.x + xv.y*rv.y + xv.z*rv.z + xv.w*rv.w;
    }
    #pragma unroll
    for (int o = 16; o; o >>= 1) {
        dg += __shfl_xor_sync(0xffffffffu, dg, o);
        dr += __shfl_xor_sync(0xffffffffu, dr, o);
    }
    if (lane == 0) {
        const float sc = 1.0f/4096.0f;
        float gl = dg*sc + gate_bias[r];
        float gs = 1.0f/(1.0f + expf(-gl));
        g_gate[b*Rr + r] = (gs >= 0.001f) ? gs : 0.0f;
        float rl = dr*sc + ret_bias[r];
        g_ret[b*Rr + r] = 1.0f/(1.0f + expf(-rl));
    }
}

// ---------------------------------------------------------------------------
// HMMA GEMM: C[128x128 tile] += A(hi/lo) x B(hi/lo)^T with bf16x3 split.
// A: [M][K] bf16 pair, B: [N][K] bf16 pair (both K-contiguous). 256 threads,
// 8 warps as 2(M)x4(N), warp tile 64x32, k-step 64, 3-stage cp.async pipeline.
template<int KT, bool GATED>
__global__ void __launch_bounds__(256) gemm_hmma(
    const __nv_bfloat16* __restrict__ Ahi, const __nv_bfloat16* __restrict__ Alo,
    const __nv_bfloat16* __restrict__ Bhi, const __nv_bfloat16* __restrict__ Blo,
    float* __restrict__ C, int ldc)
{
    constexpr int KK = KT*64;
    extern __shared__ char smem[];
    uint32_t sb = smem_u32(smem);
    const int tid = threadIdx.x;
    const int lane = tid & 31;
    const int wid = tid >> 5;
    const int warpM = wid >> 2;       // 0..1
    const int warpN = wid & 3;        // 0..3
    const int ctaN = blockIdx.x;      // N/128
    const int ctaM = blockIdx.y;      // M/128

    float acc[4][4][4];
    #pragma unroll
    for (int i = 0; i < 4; i++)
        #pragma unroll
        for (int j = 0; j < 4; j++)
            #pragma unroll
            for (int q = 0; q < 4; q++) acc[i][j][q] = 0.f;

    auto load_stage = [&](int kt, int buf) {
        uint32_t st = sb + buf*65536;
        #pragma unroll
        for (int i = 0; i < 4; i++) {
            int c = tid + i*256;            // 0..1023
            int row = c >> 3, u = c & 7;
            uint32_t sw = SWZ((uint32_t)(row*128 + u*16));
            size_t ga = (size_t)(ctaM*128 + row)*KK + kt*64 + u*8;
            size_t gb = (size_t)(ctaN*128 + row)*KK + kt*64 + u*8;
            CP16(st + sw,         (const char*)(Ahi + ga));
            CP16(st + 16384 + sw, (const char*)(Alo + ga));
            CP16(st + 32768 + sw, (const char*)(Bhi + gb));
            CP16(st + 49152 + sw, (const char*)(Blo + gb));
        }
    };

    load_stage(0, 0); CP_COMMIT();
    if (KT > 1) load_stage(1, 1);
    CP_COMMIT();

    // per-lane ldmatrix byte offsets (pre-swizzle)
    const uint32_t aOff = (uint32_t)((warpM*64 + (lane & 15))*128 + (lane >> 4)*16);
    const uint32_t bOff = (uint32_t)((warpN*32 + (lane & 7) + ((lane >> 4) & 1)*8)*128
                                     + ((lane >> 3) & 1)*16);

    for (int kt = 0; kt < KT; kt++) {
        CP_WAIT1();
        __syncthreads();
        if (kt + 2 < KT) load_stage(kt + 2, (kt + 2) % 3);
        CP_COMMIT();

        uint32_t stA = sb + (kt % 3)*65536;
        uint32_t stB = stA + 32768;
        #pragma unroll
        for (int kk = 0; kk < 4; kk++) {
            uint32_t ah[4][4], al[4][4], bh[2][4], bl[2][4];
            #pragma unroll
            for (int mf = 0; mf < 4; mf++) {
                uint32_t o = SWZ(aOff + mf*2048 + kk*32);
                ldsm4(ah[mf], stA + o);
                ldsm4(al[mf], stA + 16384 + o);
            }
            #pragma unroll
            for (int nf2 = 0; nf2 < 2; nf2++) {
                uint32_t o = SWZ(bOff + nf2*2048 + kk*32);
                ldsm4(bh[nf2], stB + o);
                ldsm4(bl[nf2], stB + 16384 + o);
            }
            #pragma unroll
            for (int mf = 0; mf < 4; mf++)
                #pragma unroll
                for (int nf = 0; nf < 4; nf++) {
                    const uint32_t* bph = &bh[nf >> 1][(nf & 1)*2];
                    const uint32_t* bpl = &bl[nf >> 1][(nf & 1)*2];
                    mma16816(acc[mf][nf], ah[mf], bph);
                    mma16816(acc[mf][nf], al[mf], bph);
                    mma16816(acc[mf][nf], ah[mf], bpl);
                }
        }
        __syncthreads();
    }

    // epilogue
    int bIdx = ctaM >> 5;   // batch (32 M-tiles per batch) — only used when GATED
    #pragma unroll
    for (int nf = 0; nf < 4; nf++) {
        int n = ctaN*128 + warpN*32 + nf*8 + (lane & 3)*2;
        float g0 = 1.f, g1 = 1.f;
        if (GATED) {
            g0 = g_gate[bIdx*Rr + n];
            g1 = g_gate[bIdx*Rr + n + 1];
        }
        #pragma unroll
        for (int mf = 0; mf < 4; mf++) {
            int m = ctaM*128 + warpM*64 + mf*16 + (lane >> 2);
            float2 v0 = make_float2(acc[mf][nf][0]*g0, acc[mf][nf][1]*g1);
            float2 v1 = make_float2(acc[mf][nf][2]*g0, acc[mf][nf][3]*g1);
            *(float2*)(C + (size_t)m*ldc + n) = v0;
            *(float2*)(C + (size_t)(m + 8)*ldc + n) = v1;
        }
    }
}

// ---------------------------------------------------------------------------
// Scan stages
__global__ void scanA_kernel() {
    int c = blockIdx.x, b = blockIdx.y;
    int r = threadIdx.x;
    float ret = g_ret[b*Rr + r];
    float* base = g_sig + ((size_t)(b*Ss + c*CLEN))*Rr + r;
    float a = 0.f;
    #pragma unroll 8
    for (int t = 0; t < CLEN; t++) {
        float s = base[(size_t)t*Rr];
        a = fmaf(a, ret, s);
        base[(size_t)t*Rr] = a;
    }
    g_carrySum[(size_t)(b*CHUNKS + c)*Rr + r] = a;
}
__global__ void scanB_kernel(const float* __restrict__ prev,
                             float* __restrict__ final_state) {
    int b = blockIdx.x, r = threadIdx.x;
    float ret = g_ret[b*Rr + r];
    float p = ret;
    #pragma unroll
    for (int i = 0; i < 6; i++) p *= p;   // ret^64
    float carry = prev[b*Rr + r];
    #pragma unroll 4
    for (int c = 0; c < CHUNKS; c++) {
        g_carryIn[(size_t)(b*CHUNKS + c)*Rr + r] = carry;
        carry = fmaf(carry, p, g_carrySum[(size_t)(b*CHUNKS + c)*Rr + r]);
    }
    final_state[b*Rr + r] = carry;
}
// scanC: apply carry and emit bf16 hi/lo of accumulated (GEMM2 operand).
__global__ void scanC_kernel() {
    int c = blockIdx.x, b = blockIdx.y;
    int r = threadIdx.x;
    float ret = g_ret[b*Rr + r];
    float cin = g_carryIn[(size_t)(b*CHUNKS + c)*Rr + r];
    float mlt = ret;
    size_t base = ((size_t)(b*Ss + c*CLEN))*Rr + r;
    #pragma unroll 8
    for (int t = 0; t < CLEN; t++) {
        float v = fmaf(cin, mlt, g_sig[base + (size_t)t*Rr]);
        unsigned short h, l;
        split1(v, h, l);
        ((unsigned short*)g_acc_hi)[base + (size_t)t*Rr] = h;
        ((unsigned short*)g_acc_lo)[base + (size_t)t*Rr] = l;
        mlt *= ret;
    }
}

// ---------------------------------------------------------------------------
#define GEMM_SMEM (3*65536)

extern "C" void kernel_launch(void* const* d_in, const int* in_sizes, int n_in,
                              void* d_out, int out_size) {
    const float* x     = (const float*)d_in[0];
    const float* prev  = (const float*)d_in[1];
    const float* freq  = (const float*)d_in[2];
    const float* rbias = (const float*)d_in[3];
    const float* rw    = (const float*)d_in[4];
    const float* gw    = (const float*)d_in[5];
    const float* gbias = (const float*)d_in[6];
    const float* outw  = (const float*)d_in[7];
    float* out = (float*)d_out;
    float* final_state = out + (size_t)Mtot*Dd;

    cudaFuncSetAttribute(gemm_hmma<16,true>,  cudaFuncAttributeMaxDynamicSharedMemorySize, GEMM_SMEM);
    cudaFuncSetAttribute(gemm_hmma<4,false>,  cudaFuncAttributeMaxDynamicSharedMemorySize, GEMM_SMEM);

    // device symbol addresses (host-side queries; graph-capture safe)
    __nv_bfloat16 *xhi, *xlo, *fhi, *flo, *ohi, *olo, *ahi, *alo;
    cudaGetSymbolAddress((void**)&xhi, g_x_hi);
    cudaGetSymbolAddress((void**)&xlo, g_x_lo);
    cudaGetSymbolAddress((void**)&fhi, g_fnorm_hi);
    cudaGetSymbolAddress((void**)&flo, g_fnorm_lo);
    cudaGetSymbolAddress((void**)&ohi, g_outw_hi);
    cudaGetSymbolAddress((void**)&olo, g_outw_lo);
    cudaGetSymbolAddress((void**)&ahi, g_acc_hi);
    cudaGetSymbolAddress((void**)&alo, g_acc_lo);
    float* sig;
    cudaGetSymbolAddress((void**)&sig, g_sig);

    fnorm_kernel<<<Rr, 256>>>(freq);
    outw_split_kernel<<<256, 256>>>(outw);
    xhat_kernel<<<Mtot, 256>>>(x);
    xm_part_kernel<<<dim3(32, Bb), 256>>>(x);
    xm_reduce_kernel<<<Bb, 1024>>>();
    gates_kernel<<<256, 256>>>(gw, gbias, rw, rbias);

    // GEMM1: sig = (xhat . fnorm^T) * gate   — M=32768, N=256, K=1024
    gemm_hmma<16,true><<<dim3(Rr/128, Mtot/128), 256, GEMM_SMEM>>>(
        xhi, xlo, fhi, flo, sig, Rr);

    scanA_kernel<<<dim3(CHUNKS, Bb), 256>>>();
    scanB_kernel<<<Bb, Rr>>>(prev, final_state);
    scanC_kernel<<<dim3(CHUNKS, Bb), 256>>>();

    // GEMM2: out = acc . out_w^T — M=32768, N=1024, K=256
    gemm_hmma<4,false><<<dim3(Dd/128, Mtot/128), 256, GEMM_SMEM>>>(
        ahi, alo, ohi, olo, out, Dd);
}

// round 6
// speedup vs baseline: 2.4500x; 1.1536x over previous
#include <cuda_runtime.h>
#include <cuda_bf16.h>
#include <math.h>
#include <stdint.h>

// Problem constants
#define Bb 8
#define Ss 4096
#define Dd 1024
#define Rr 256
#define Mtot (Bb*Ss)      // 32768
#define CHUNKS 64
#define CLEN 64
#define XROWS 16          // rows per xprep block
#define XBLKS (Mtot/XROWS)   // 2048

// ---------------------------------------------------------------------------
// Static device scratch
__device__ __nv_bfloat16 g_x_hi[(size_t)Mtot*Dd];     // raw x hi
__device__ __nv_bfloat16 g_x_lo[(size_t)Mtot*Dd];     // raw x lo
__device__ float g_invnorm[Mtot];
__device__ __nv_bfloat16 g_fnorm_hi[Rr*Dd];
__device__ __nv_bfloat16 g_fnorm_lo[Rr*Dd];
__device__ __nv_bfloat16 g_outw_hi[Dd*Rr];
__device__ __nv_bfloat16 g_outw_lo[Dd*Rr];
__device__ __nv_bfloat16 g_acc_hi[(size_t)Mtot*Rr];
__device__ __nv_bfloat16 g_acc_lo[(size_t)Mtot*Rr];
__device__ float g_xm_part[(size_t)XBLKS*Dd];         // 8 MB partial col sums
__device__ float g_xm[Bb*Dd];
__device__ float g_gate[Bb*Rr];
__device__ float g_ret[Bb*Rr];
__device__ float g_sig[(size_t)Mtot*Rr];
__device__ float g_carrySum[Bb*CHUNKS*Rr];
__device__ float g_carryIn[Bb*CHUNKS*Rr];

// ---------------------------------------------------------------------------
// PTX helpers (sm_100-plain legal: cp.async / ldmatrix / mma.sync)
__device__ __forceinline__ uint32_t smem_u32(const void* p) {
    uint32_t a;
    asm("{ .reg .u64 t; cvta.to.shared.u64 t, %1; cvt.u32.u64 %0, t; }" : "=r"(a) : "l"(p));
    return a;
}
#define CP16(dst, src)  asm volatile("cp.async.cg.shared.global [%0], [%1], 16;" :: "r"(dst), "l"(src) : "memory")
#define CP_COMMIT()     asm volatile("cp.async.commit_group;" ::: "memory")
#define CP_WAIT1()      asm volatile("cp.async.wait_group 1;" ::: "memory")

__device__ __forceinline__ void ldsm4(uint32_t* r, uint32_t addr) {
    asm volatile("ldmatrix.sync.aligned.m8n8.x4.shared.b16 {%0,%1,%2,%3}, [%4];"
        : "=r"(r[0]), "=r"(r[1]), "=r"(r[2]), "=r"(r[3]) : "r"(addr));
}
__device__ __forceinline__ void mma16816(float* c, const uint32_t* a, const uint32_t* b) {
    asm volatile("mma.sync.aligned.m16n8k16.row.col.f32.bf16.bf16.f32 "
        "{%0,%1,%2,%3}, {%4,%5,%6,%7}, {%8,%9}, {%0,%1,%2,%3};"
        : "+f"(c[0]), "+f"(c[1]), "+f"(c[2]), "+f"(c[3])
        : "r"(a[0]), "r"(a[1]), "r"(a[2]), "r"(a[3]), "r"(b[0]), "r"(b[1]));
}
#define SWZ(o) ((o) ^ (((o) >> 3) & 0x70))

// bf16 hi/lo split
__device__ __forceinline__ void split1(float v, unsigned short& h, unsigned short& l) {
    __nv_bfloat16 hb = __float2bfloat16_rn(v);
    float r = v - __bfloat162float(hb);
    __nv_bfloat16 lb = __float2bfloat16_rn(r);
    h = *reinterpret_cast<unsigned short*>(&hb);
    l = *reinterpret_cast<unsigned short*>(&lb);
}
__device__ __forceinline__ void split4(float4 v, unsigned long long& hv, unsigned long long& lv) {
    unsigned short h0,h1,h2,h3,l0,l1,l2,l3;
    split1(v.x,h0,l0); split1(v.y,h1,l1); split1(v.z,h2,l2); split1(v.w,h3,l3);
    hv = (unsigned long long)h0 | ((unsigned long long)h1<<16) |
         ((unsigned long long)h2<<32) | ((unsigned long long)h3<<48);
    lv = (unsigned long long)l0 | ((unsigned long long)l1<<16) |
         ((unsigned long long)l2<<32) | ((unsigned long long)l3<<48);
}

// ---------------------------------------------------------------------------
// xprep: single pass over x. Produces raw bf16 hi/lo split, per-row invnorm,
// and per-block column-sum partials. 16 rows/block, 256 threads.
__global__ void __launch_bounds__(256) xprep_kernel(const float* __restrict__ x) {
    __shared__ float ws[XROWS][8];
    int blk = blockIdx.x;
    int tid = threadIdx.x;
    int w = tid >> 5, l = tid & 31;
    size_t m0 = (size_t)blk * XROWS;
    float4 colsum = make_float4(0.f, 0.f, 0.f, 0.f);

    #pragma unroll 4
    for (int r = 0; r < XROWS; r++) {
        float4 v = ((const float4*)(x + (m0 + r)*Dd))[tid];
        colsum.x += v.x; colsum.y += v.y; colsum.z += v.z; colsum.w += v.w;
        float s = v.x*v.x + v.y*v.y + v.z*v.z + v.w*v.w;
        #pragma unroll
        for (int o = 16; o; o >>= 1) s += __shfl_xor_sync(0xffffffffu, s, o);
        if (l == 0) ws[r][w] = s;
        unsigned long long hv, lv;
        split4(v, hv, lv);
        *(unsigned long long*)(g_x_hi + (m0 + r)*Dd + tid*4) = hv;
        *(unsigned long long*)(g_x_lo + (m0 + r)*Dd + tid*4) = lv;
    }
    ((float4*)(g_xm_part + (size_t)blk*Dd))[tid] = colsum;
    __syncthreads();
    if (tid < XROWS) {
        float t = 0.f;
        #pragma unroll
        for (int i = 0; i < 8; i++) t += ws[tid][i];
        g_invnorm[m0 + tid] = 1.0f / fmaxf(sqrtf(t), 1e-12f);
    }
}

// f_norm split
__global__ void fnorm_kernel(const float* __restrict__ freq) {
    int r = blockIdx.x;
    int tid = threadIdx.x;
    float4 v = ((const float4*)(freq + (size_t)r*Dd))[tid];
    float s = v.x*v.x + v.y*v.y + v.z*v.z + v.w*v.w;
    #pragma unroll
    for (int o = 16; o; o >>= 1) s += __shfl_xor_sync(0xffffffffu, s, o);
    __shared__ float ws[8];
    __shared__ float invs;
    int w = tid >> 5, l = tid & 31;
    if (l == 0) ws[w] = s;
    __syncthreads();
    if (tid == 0) {
        float t = 0.f;
        #pragma unroll
        for (int i = 0; i < 8; i++) t += ws[i];
        invs = 1.0f / fmaxf(sqrtf(t), 1e-12f);
    }
    __syncthreads();
    float iv = invs;
    float4 n = make_float4(v.x*iv, v.y*iv, v.z*iv, v.w*iv);
    unsigned long long hv, lv;
    split4(n, hv, lv);
    *(unsigned long long*)(g_fnorm_hi + (size_t)r*Dd + tid*4) = hv;
    *(unsigned long long*)(g_fnorm_lo + (size_t)r*Dd + tid*4) = lv;
}

__global__ void outw_split_kernel(const float* __restrict__ w) {
    int idx = (blockIdx.x*256 + threadIdx.x)*4;
    float4 v = *(const float4*)(w + idx);
    unsigned long long hv, lv;
    split4(v, hv, lv);
    *(unsigned long long*)(g_outw_hi + idx) = hv;
    *(unsigned long long*)(g_outw_lo + idx) = lv;
}

// xm reduce: 256 partials per batch
__global__ void xm_reduce_kernel() {
    int b = blockIdx.x, d = threadIdx.x;
    const int PPB = XBLKS / Bb;   // 256 partial blocks per batch
    float s = 0.f;
    #pragma unroll 8
    for (int c = 0; c < PPB; c++)
        s += g_xm_part[(size_t)(b*PPB + c)*Dd + d];
    g_xm[(size_t)b*Dd + d] = s;
}

__global__ void gates_kernel(const float* __restrict__ gate_w,
                             const float* __restrict__ gate_bias,
                             const float* __restrict__ ret_w,
                             const float* __restrict__ ret_bias) {
    int gw = (blockIdx.x*blockDim.x + threadIdx.x) >> 5;
    int lane = threadIdx.x & 31;
    int b = gw >> 8, r = gw & 255;
    const float4* xm4 = (const float4*)(g_xm + (size_t)b*Dd);
    const float4* gw4 = (const float4*)(gate_w + (size_t)r*Dd);
    const float4* rw4 = (const float4*)(ret_w + (size_t)r*Dd);
    float dg = 0.f, dr = 0.f;
    #pragma unroll
    for (int i = 0; i < 8; i++) {
        int k = i*32 + lane;
        float4 xv = xm4[k], gv = gw4[k], rv = rw4[k];
        dg += xv.x*gv.x + xv.y*gv.y + xv.z*gv.z + xv.w*gv.w;
        dr += xv.x*rv.x + xv.y*rv.y + xv.z*rv.z + xv.w*rv.w;
    }
    #pragma unroll
    for (int o = 16; o; o >>= 1) {
        dg += __shfl_xor_sync(0xffffffffu, dg, o);
        dr += __shfl_xor_sync(0xffffffffu, dr, o);
    }
    if (lane == 0) {
        const float sc = 1.0f/4096.0f;
        float gl = dg*sc + gate_bias[r];
        float gs = 1.0f/(1.0f + expf(-gl));
        g_gate[b*Rr + r] = (gs >= 0.001f) ? gs : 0.0f;
        float rl = dr*sc + ret_bias[r];
        g_ret[b*Rr + r] = 1.0f/(1.0f + expf(-rl));
    }
}

// ---------------------------------------------------------------------------
// HMMA GEMM: C[128x128 tile] += A(hi/lo) x B(hi/lo)^T with bf16x3 split.
// GATED variant additionally multiplies rows by invnorm[m] and cols by gate[b,n].
template<int KT, bool GATED>
__global__ void __launch_bounds__(256) gemm_hmma(
    const __nv_bfloat16* __restrict__ Ahi, const __nv_bfloat16* __restrict__ Alo,
    const __nv_bfloat16* __restrict__ Bhi, const __nv_bfloat16* __restrict__ Blo,
    float* __restrict__ C, int ldc)
{
    constexpr int KK = KT*64;
    extern __shared__ char smem[];
    uint32_t sb = smem_u32(smem);
    const int tid = threadIdx.x;
    const int lane = tid & 31;
    const int wid = tid >> 5;
    const int warpM = wid >> 2;
    const int warpN = wid & 3;
    const int ctaN = blockIdx.x;
    const int ctaM = blockIdx.y;

    float acc[4][4][4];
    #pragma unroll
    for (int i = 0; i < 4; i++)
        #pragma unroll
        for (int j = 0; j < 4; j++)
            #pragma unroll
            for (int q = 0; q < 4; q++) acc[i][j][q] = 0.f;

    auto load_stage = [&](int kt, int buf) {
        uint32_t st = sb + buf*65536;
        #pragma unroll
        for (int i = 0; i < 4; i++) {
            int c = tid + i*256;
            int row = c >> 3, u = c & 7;
            uint32_t sw = SWZ((uint32_t)(row*128 + u*16));
            size_t ga = (size_t)(ctaM*128 + row)*KK + kt*64 + u*8;
            size_t gb = (size_t)(ctaN*128 + row)*KK + kt*64 + u*8;
            CP16(st + sw,         (const char*)(Ahi + ga));
            CP16(st + 16384 + sw, (const char*)(Alo + ga));
            CP16(st + 32768 + sw, (const char*)(Bhi + gb));
            CP16(st + 49152 + sw, (const char*)(Blo + gb));
        }
    };

    load_stage(0, 0); CP_COMMIT();
    if (KT > 1) load_stage(1, 1);
    CP_COMMIT();

    const uint32_t aOff = (uint32_t)((warpM*64 + (lane & 15))*128 + (lane >> 4)*16);
    const uint32_t bOff = (uint32_t)((warpN*32 + (lane & 7) + ((lane >> 4) & 1)*8)*128
                                     + ((lane >> 3) & 1)*16);

    for (int kt = 0; kt < KT; kt++) {
        CP_WAIT1();
        __syncthreads();
        if (kt + 2 < KT) load_stage(kt + 2, (kt + 2) % 3);
        CP_COMMIT();

        uint32_t stA = sb + (kt % 3)*65536;
        uint32_t stB = stA + 32768;
        #pragma unroll
        for (int kk = 0; kk < 4; kk++) {
            uint32_t ah[4][4], al[4][4], bh[2][4], bl[2][4];
            #pragma unroll
            for (int mf = 0; mf < 4; mf++) {
                uint32_t o = SWZ(aOff + mf*2048 + kk*32);
                ldsm4(ah[mf], stA + o);
                ldsm4(al[mf], stA + 16384 + o);
            }
            #pragma unroll
            for (int nf2 = 0; nf2 < 2; nf2++) {
                uint32_t o = SWZ(bOff + nf2*2048 + kk*32);
                ldsm4(bh[nf2], stB + o);
                ldsm4(bl[nf2], stB + 16384 + o);
            }
            #pragma unroll
            for (int mf = 0; mf < 4; mf++)
                #pragma unroll
                for (int nf = 0; nf < 4; nf++) {
                    const uint32_t* bph = &bh[nf >> 1][(nf & 1)*2];
                    const uint32_t* bpl = &bl[nf >> 1][(nf & 1)*2];
                    mma16816(acc[mf][nf], ah[mf], bph);
                    mma16816(acc[mf][nf], al[mf], bph);
                    mma16816(acc[mf][nf], ah[mf], bpl);
                }
        }
        __syncthreads();
    }

    // epilogue
    int bIdx = ctaM >> 5;
    float inv0[4], inv1[4];
    if (GATED) {
        #pragma unroll
        for (int mf = 0; mf < 4; mf++) {
            int m = ctaM*128 + warpM*64 + mf*16 + (lane >> 2);
            inv0[mf] = g_invnorm[m];
            inv1[mf] = g_invnorm[m + 8];
        }
    }
    #pragma unroll
    for (int nf = 0; nf < 4; nf++) {
        int n = ctaN*128 + warpN*32 + nf*8 + (lane & 3)*2;
        float g0 = 1.f, g1 = 1.f;
        if (GATED) {
            g0 = g_gate[bIdx*Rr + n];
            g1 = g_gate[bIdx*Rr + n + 1];
        }
        #pragma unroll
        for (int mf = 0; mf < 4; mf++) {
            int m = ctaM*128 + warpM*64 + mf*16 + (lane >> 2);
            float i0 = GATED ? inv0[mf] : 1.f;
            float i1 = GATED ? inv1[mf] : 1.f;
            float2 v0 = make_float2(acc[mf][nf][0]*g0*i0, acc[mf][nf][1]*g1*i0);
            float2 v1 = make_float2(acc[mf][nf][2]*g0*i1, acc[mf][nf][3]*g1*i1);
            *(float2*)(C + (size_t)m*ldc + n) = v0;
            *(float2*)(C + (size_t)(m + 8)*ldc + n) = v1;
        }
    }
}

// ---------------------------------------------------------------------------
// Scan stages
__global__ void scanA_kernel() {
    int c = blockIdx.x, b = blockIdx.y;
    int r = threadIdx.x;
    float ret = g_ret[b*Rr + r];
    float* base = g_sig + ((size_t)(b*Ss + c*CLEN))*Rr + r;
    float a = 0.f;
    #pragma unroll 8
    for (int t = 0; t < CLEN; t++) {
        float s = base[(size_t)t*Rr];
        a = fmaf(a, ret, s);
        base[(size_t)t*Rr] = a;
    }
    g_carrySum[(size_t)(b*CHUNKS + c)*Rr + r] = a;
}
__global__ void scanB_kernel(const float* __restrict__ prev,
                             float* __restrict__ final_state) {
    int b = blockIdx.x, r = threadIdx.x;
    float ret = g_ret[b*Rr + r];
    float p = ret;
    #pragma unroll
    for (int i = 0; i < 6; i++) p *= p;   // ret^64
    float carry = prev[b*Rr + r];
    #pragma unroll 4
    for (int c = 0; c < CHUNKS; c++) {
        g_carryIn[(size_t)(b*CHUNKS + c)*Rr + r] = carry;
        carry = fmaf(carry, p, g_carrySum[(size_t)(b*CHUNKS + c)*Rr + r]);
    }
    final_state[b*Rr + r] = carry;
}
__global__ void scanC_kernel() {
    int c = blockIdx.x, b = blockIdx.y;
    int r = threadIdx.x;
    float ret = g_ret[b*Rr + r];
    float cin = g_carryIn[(size_t)(b*CHUNKS + c)*Rr + r];
    float mlt = ret;
    size_t base = ((size_t)(b*Ss + c*CLEN))*Rr + r;
    #pragma unroll 8
    for (int t = 0; t < CLEN; t++) {
        float v = fmaf(cin, mlt, g_sig[base + (size_t)t*Rr]);
        unsigned short h, l;
        split1(v, h, l);
        ((unsigned short*)g_acc_hi)[base + (size_t)t*Rr] = h;
        ((unsigned short*)g_acc_lo)[base + (size_t)t*Rr] = l;
        mlt *= ret;
    }
}

// ---------------------------------------------------------------------------
#define GEMM_SMEM (3*65536)

extern "C" void kernel_launch(void* const* d_in, const int* in_sizes, int n_in,
                              void* d_out, int out_size) {
    const float* x     = (const float*)d_in[0];
    const float* prev  = (const float*)d_in[1];
    const float* freq  = (const float*)d_in[2];
    const float* rbias = (const float*)d_in[3];
    const float* rw    = (const float*)d_in[4];
    const float* gw    = (const float*)d_in[5];
    const float* gbias = (const float*)d_in[6];
    const float* outw  = (const float*)d_in[7];
    float* out = (float*)d_out;
    float* final_state = out + (size_t)Mtot*Dd;

    cudaFuncSetAttribute(gemm_hmma<16,true>,  cudaFuncAttributeMaxDynamicSharedMemorySize, GEMM_SMEM);
    cudaFuncSetAttribute(gemm_hmma<4,false>,  cudaFuncAttributeMaxDynamicSharedMemorySize, GEMM_SMEM);

    __nv_bfloat16 *xhi, *xlo, *fhi, *flo, *ohi, *olo, *ahi, *alo;
    cudaGetSymbolAddress((void**)&xhi, g_x_hi);
    cudaGetSymbolAddress((void**)&xlo, g_x_lo);
    cudaGetSymbolAddress((void**)&fhi, g_fnorm_hi);
    cudaGetSymbolAddress((void**)&flo, g_fnorm_lo);
    cudaGetSymbolAddress((void**)&ohi, g_outw_hi);
    cudaGetSymbolAddress((void**)&olo, g_outw_lo);
    cudaGetSymbolAddress((void**)&ahi, g_acc_hi);
    cudaGetSymbolAddress((void**)&alo, g_acc_lo);
    float* sig;
    cudaGetSymbolAddress((void**)&sig, g_sig);

    fnorm_kernel<<<Rr, 256>>>(freq);
    outw_split_kernel<<<256, 256>>>(outw);
    xprep_kernel<<<XBLKS, 256>>>(x);
    xm_reduce_kernel<<<Bb, 1024>>>();
    gates_kernel<<<256, 256>>>(gw, gbias, rw, rbias);

    // GEMM1: sig = (x . fnorm^T) * invnorm[m] * gate[b,r]
    gemm_hmma<16,true><<<dim3(Rr/128, Mtot/128), 256, GEMM_SMEM>>>(
        xhi, xlo, fhi, flo, sig, Rr);

    scanA_kernel<<<dim3(CHUNKS, Bb), 256>>>();
    scanB_kernel<<<Bb, Rr>>>(prev, final_state);
    scanC_kernel<<<dim3(CHUNKS, Bb), 256>>>();

    // GEMM2: out = acc . out_w^T
    gemm_hmma<4,false><<<dim3(Dd/128, Mtot/128), 256, GEMM_SMEM>>>(
        ahi, alo, ohi, olo, out, Dd);
}

// round 9
// speedup vs baseline: 2.4618x; 1.0048x over previous
#include <cuda_runtime.h>
#include <cuda_bf16.h>
#include <math.h>
#include <stdint.h>

// Problem constants
#define Bb 8
#define Ss 4096
#define Dd 1024
#define Rr 256
#define Mtot (Bb*Ss)      // 32768
#define CHUNKS 64
#define CLEN 64
#define XROWS 16
#define XBLKS (Mtot/XROWS)   // 2048

// ---------------------------------------------------------------------------
// Static device scratch
__device__ __nv_bfloat16 g_x_hi[(size_t)Mtot*Dd];
__device__ __nv_bfloat16 g_x_lo[(size_t)Mtot*Dd];
__device__ float g_invnorm[Mtot];
__device__ __nv_bfloat16 g_fnorm_hi[Rr*Dd];
__device__ __nv_bfloat16 g_fnorm_lo[Rr*Dd];
__device__ __nv_bfloat16 g_outw_hi[Dd*Rr];
__device__ __nv_bfloat16 g_outw_lo[Dd*Rr];
__device__ __nv_bfloat16 g_acc_hi[(size_t)Mtot*Rr];
__device__ __nv_bfloat16 g_acc_lo[(size_t)Mtot*Rr];
__device__ float g_xm_part[(size_t)XBLKS*Dd];
__device__ float g_xm[Bb*Dd];
__device__ float g_gate[Bb*Rr];
__device__ float g_ret[Bb*Rr];
__device__ float g_sig[(size_t)Mtot*Rr];
__device__ float g_carrySum[Bb*CHUNKS*Rr];
__device__ float g_carryIn[Bb*CHUNKS*Rr];

// ---------------------------------------------------------------------------
// PTX helpers
__device__ __forceinline__ uint32_t smem_u32(const void* p) {
    uint32_t a;
    asm("{ .reg .u64 t; cvta.to.shared.u64 t, %1; cvt.u32.u64 %0, t; }" : "=r"(a) : "l"(p));
    return a;
}
#define CP16(dst, src)  asm volatile("cp.async.cg.shared.global [%0], [%1], 16;" :: "r"(dst), "l"(src) : "memory")
#define CP_COMMIT()     asm volatile("cp.async.commit_group;" ::: "memory")
#define CP_WAIT1()      asm volatile("cp.async.wait_group 1;" ::: "memory")

__device__ __forceinline__ void ldsm4(uint32_t* r, uint32_t addr) {
    asm volatile("ldmatrix.sync.aligned.m8n8.x4.shared.b16 {%0,%1,%2,%3}, [%4];"
        : "=r"(r[0]), "=r"(r[1]), "=r"(r[2]), "=r"(r[3]) : "r"(addr));
}
__device__ __forceinline__ void mma16816(float* c, const uint32_t* a, const uint32_t* b) {
    asm volatile("mma.sync.aligned.m16n8k16.row.col.f32.bf16.bf16.f32 "
        "{%0,%1,%2,%3}, {%4,%5,%6,%7}, {%8,%9}, {%0,%1,%2,%3};"
        : "+f"(c[0]), "+f"(c[1]), "+f"(c[2]), "+f"(c[3])
        : "r"(a[0]), "r"(a[1]), "r"(a[2]), "r"(a[3]), "r"(b[0]), "r"(b[1]));
}
#define SWZ(o) ((o) ^ (((o) >> 3) & 0x70))

// bf16 hi/lo split
__device__ __forceinline__ void split1(float v, unsigned short& h, unsigned short& l) {
    __nv_bfloat16 hb = __float2bfloat16_rn(v);
    float r = v - __bfloat162float(hb);
    __nv_bfloat16 lb = __float2bfloat16_rn(r);
    h = *reinterpret_cast<unsigned short*>(&hb);
    l = *reinterpret_cast<unsigned short*>(&lb);
}
__device__ __forceinline__ void split4(float4 v, unsigned long long& hv, unsigned long long& lv) {
    unsigned short h0,h1,h2,h3,l0,l1,l2,l3;
    split1(v.x,h0,l0); split1(v.y,h1,l1); split1(v.z,h2,l2); split1(v.w,h3,l3);
    hv = (unsigned long long)h0 | ((unsigned long long)h1<<16) |
         ((unsigned long long)h2<<32) | ((unsigned long long)h3<<48);
    lv = (unsigned long long)l0 | ((unsigned long long)l1<<16) |
         ((unsigned long long)l2<<32) | ((unsigned long long)l3<<48);
}

// ---------------------------------------------------------------------------
// xprep: single pass over x -> raw bf16 hi/lo, invnorm, column-sum partials.
__global__ void __launch_bounds__(256) xprep_kernel(const float* __restrict__ x) {
    __shared__ float ws[XROWS][8];
    int blk = blockIdx.x;
    int tid = threadIdx.x;
    int w = tid >> 5, l = tid & 31;
    size_t m0 = (size_t)blk * XROWS;
    float4 colsum = make_float4(0.f, 0.f, 0.f, 0.f);

    #pragma unroll 4
    for (int r = 0; r < XROWS; r++) {
        float4 v = ((const float4*)(x + (m0 + r)*Dd))[tid];
        colsum.x += v.x; colsum.y += v.y; colsum.z += v.z; colsum.w += v.w;
        float s = v.x*v.x + v.y*v.y + v.z*v.z + v.w*v.w;
        #pragma unroll
        for (int o = 16; o; o >>= 1) s += __shfl_xor_sync(0xffffffffu, s, o);
        if (l == 0) ws[r][w] = s;
        unsigned long long hv, lv;
        split4(v, hv, lv);
        *(unsigned long long*)(g_x_hi + (m0 + r)*Dd + tid*4) = hv;
        *(unsigned long long*)(g_x_lo + (m0 + r)*Dd + tid*4) = lv;
    }
    ((float4*)(g_xm_part + (size_t)blk*Dd))[tid] = colsum;
    __syncthreads();
    if (tid < XROWS) {
        float t = 0.f;
        #pragma unroll
        for (int i = 0; i < 8; i++) t += ws[tid][i];
        g_invnorm[m0 + tid] = 1.0f / fmaxf(sqrtf(t), 1e-12f);
    }
}

__global__ void fnorm_kernel(const float* __restrict__ freq) {
    int r = blockIdx.x;
    int tid = threadIdx.x;
    float4 v = ((const float4*)(freq + (size_t)r*Dd))[tid];
    float s = v.x*v.x + v.y*v.y + v.z*v.z + v.w*v.w;
    #pragma unroll
    for (int o = 16; o; o >>= 1) s += __shfl_xor_sync(0xffffffffu, s, o);
    __shared__ float ws[8];
    __shared__ float invs;
    int w = tid >> 5, l = tid & 31;
    if (l == 0) ws[w] = s;
    __syncthreads();
    if (tid == 0) {
        float t = 0.f;
        #pragma unroll
        for (int i = 0; i < 8; i++) t += ws[i];
        invs = 1.0f / fmaxf(sqrtf(t), 1e-12f);
    }
    __syncthreads();
    float iv = invs;
    float4 n = make_float4(v.x*iv, v.y*iv, v.z*iv, v.w*iv);
    unsigned long long hv, lv;
    split4(n, hv, lv);
    *(unsigned long long*)(g_fnorm_hi + (size_t)r*Dd + tid*4) = hv;
    *(unsigned long long*)(g_fnorm_lo + (size_t)r*Dd + tid*4) = lv;
}

__global__ void outw_split_kernel(const float* __restrict__ w) {
    int idx = (blockIdx.x*256 + threadIdx.x)*4;
    float4 v = *(const float4*)(w + idx);
    unsigned long long hv, lv;
    split4(v, hv, lv);
    *(unsigned long long*)(g_outw_hi + idx) = hv;
    *(unsigned long long*)(g_outw_lo + idx) = lv;
}

// xm reduce: parallel over (b, 256-col slabs): 32 blocks
__global__ void xm_reduce_kernel() {
    int b = blockIdx.x >> 2;
    int d = (blockIdx.x & 3)*256 + threadIdx.x;
    const int PPB = XBLKS / Bb;   // 256
    float s = 0.f;
    #pragma unroll 8
    for (int c = 0; c < PPB; c++)
        s += g_xm_part[(size_t)(b*PPB + c)*Dd + d];
    g_xm[(size_t)b*Dd + d] = s;
}

__global__ void gates_kernel(const float* __restrict__ gate_w,
                             const float* __restrict__ gate_bias,
                             const float* __restrict__ ret_w,
                             const float* __restrict__ ret_bias) {
    int gw = (blockIdx.x*blockDim.x + threadIdx.x) >> 5;
    int lane = threadIdx.x & 31;
    int b = gw >> 8, r = gw & 255;
    const float4* xm4 = (const float4*)(g_xm + (size_t)b*Dd);
    const float4* gw4 = (const float4*)(gate_w + (size_t)r*Dd);
    const float4* rw4 = (const float4*)(ret_w + (size_t)r*Dd);
    float dg = 0.f, dr = 0.f;
    #pragma unroll
    for (int i = 0; i < 8; i++) {
        int k = i*32 + lane;
        float4 xv = xm4[k], gv = gw4[k], rv = rw4[k];
        dg += xv.x*gv.x + xv.y*gv.y + xv.z*gv.z + xv.w*gv.w;
        dr += xv.x*rv.x + xv.y*rv.y + xv.z*rv.z + xv.w*rv.w;
    }
    #pragma unroll
    for (int o = 16; o; o >>= 1) {
        dg += __shfl_xor_sync(0xffffffffu, dg, o);
        dr += __shfl_xor_sync(0xffffffffu, dr, o);
    }
    if (lane == 0) {
        const float sc = 1.0f/4096.0f;
        float gl = dg*sc + gate_bias[r];
        float gs = 1.0f/(1.0f + expf(-gl));
        g_gate[b*Rr + r] = (gs >= 0.001f) ? gs : 0.0f;
        float rl = dr*sc + ret_bias[r];
        g_ret[b*Rr + r] = 1.0f/(1.0f + expf(-rl));
    }
}

// ---------------------------------------------------------------------------
// HMMA GEMM (PROVEN R6 structure): CTA tile 128x128, k-step 64, 3-stage
// cp.async pipeline. 8 warps 2(M)x4(N), warp tile 64x32. bf16x3 split.
// Stage: Ahi 16K | Alo 16K | Bhi 16K | Blo 16K = 64KB; 3 stages = 192KB.
template<int KT, bool GATED>
__global__ void __launch_bounds__(256) gemm_hmma(
    const __nv_bfloat16* __restrict__ Ahi, const __nv_bfloat16* __restrict__ Alo,
    const __nv_bfloat16* __restrict__ Bhi, const __nv_bfloat16* __restrict__ Blo,
    float* __restrict__ C, int ldc)
{
    constexpr int KK = KT*64;
    extern __shared__ char smem[];
    uint32_t sb = smem_u32(smem);
    const int tid = threadIdx.x;
    const int lane = tid & 31;
    const int wid = tid >> 5;
    const int warpM = wid >> 2;
    const int warpN = wid & 3;
    const int ctaN = blockIdx.x;
    const int ctaM = blockIdx.y;

    float acc[4][4][4];
    #pragma unroll
    for (int i = 0; i < 4; i++)
        #pragma unroll
        for (int j = 0; j < 4; j++)
            #pragma unroll
            for (int q = 0; q < 4; q++) acc[i][j][q] = 0.f;

    auto load_stage = [&](int kt, int buf) {
        uint32_t st = sb + buf*65536;
        #pragma unroll
        for (int i = 0; i < 4; i++) {
            int c = tid + i*256;
            int row = c >> 3, u = c & 7;
            uint32_t sw = SWZ((uint32_t)(row*128 + u*16));
            size_t ga = (size_t)(ctaM*128 + row)*KK + kt*64 + u*8;
            size_t gb = (size_t)(ctaN*128 + row)*KK + kt*64 + u*8;
            CP16(st + sw,         (const char*)(Ahi + ga));
            CP16(st + 16384 + sw, (const char*)(Alo + ga));
            CP16(st + 32768 + sw, (const char*)(Bhi + gb));
            CP16(st + 49152 + sw, (const char*)(Blo + gb));
        }
    };

    load_stage(0, 0); CP_COMMIT();
    if (KT > 1) load_stage(1, 1);
    CP_COMMIT();

    const uint32_t aOff = (uint32_t)((warpM*64 + (lane & 15))*128 + (lane >> 4)*16);
    const uint32_t bOff = (uint32_t)((warpN*32 + (lane & 7) + ((lane >> 4) & 1)*8)*128
                                     + ((lane >> 3) & 1)*16);

    for (int kt = 0; kt < KT; kt++) {
        CP_WAIT1();
        __syncthreads();
        if (kt + 2 < KT) load_stage(kt + 2, (kt + 2) % 3);
        CP_COMMIT();

        uint32_t stA = sb + (kt % 3)*65536;
        uint32_t stB = stA + 32768;
        #pragma unroll
        for (int kk = 0; kk < 4; kk++) {
            uint32_t ah[4][4], al[4][4], bh[2][4], bl[2][4];
            #pragma unroll
            for (int mf = 0; mf < 4; mf++) {
                uint32_t o = SWZ(aOff + mf*2048 + kk*32);
                ldsm4(ah[mf], stA + o);
                ldsm4(al[mf], stA + 16384 + o);
            }
            #pragma unroll
            for (int nf2 = 0; nf2 < 2; nf2++) {
                uint32_t o = SWZ(bOff + nf2*2048 + kk*32);
                ldsm4(bh[nf2], stB + o);
                ldsm4(bl[nf2], stB + 16384 + o);
            }
            #pragma unroll
            for (int mf = 0; mf < 4; mf++)
                #pragma unroll
                for (int nf = 0; nf < 4; nf++) {
                    const uint32_t* bph = &bh[nf >> 1][(nf & 1)*2];
                    const uint32_t* bpl = &bl[nf >> 1][(nf & 1)*2];
                    mma16816(acc[mf][nf], ah[mf], bph);
                    mma16816(acc[mf][nf], al[mf], bph);
                    mma16816(acc[mf][nf], ah[mf], bpl);
                }
        }
        __syncthreads();
    }

    // epilogue
    int bIdx = ctaM >> 5;
    float inv0[4], inv1[4];
    if (GATED) {
        #pragma unroll
        for (int mf = 0; mf < 4; mf++) {
            int m = ctaM*128 + warpM*64 + mf*16 + (lane >> 2);
            inv0[mf] = g_invnorm[m];
            inv1[mf] = g_invnorm[m + 8];
        }
    }
    #pragma unroll
    for (int nf = 0; nf < 4; nf++) {
        int n = ctaN*128 + warpN*32 + nf*8 + (lane & 3)*2;
        float g0 = 1.f, g1 = 1.f;
        if (GATED) {
            g0 = g_gate[bIdx*Rr + n];
            g1 = g_gate[bIdx*Rr + n + 1];
        }
        #pragma unroll
        for (int mf = 0; mf < 4; mf++) {
            int m = ctaM*128 + warpM*64 + mf*16 + (lane >> 2);
            float i0 = GATED ? inv0[mf] : 1.f;
            float i1 = GATED ? inv1[mf] : 1.f;
            float2 v0 = make_float2(acc[mf][nf][0]*g0*i0, acc[mf][nf][1]*g1*i0);
            float2 v1 = make_float2(acc[mf][nf][2]*g0*i1, acc[mf][nf][3]*g1*i1);
            *(float2*)(C + (size_t)m*ldc + n) = v0;
            *(float2*)(C + (size_t)(m + 8)*ldc + n) = v1;
        }
    }
}

// ---------------------------------------------------------------------------
// Scan stages
// scanA: chunk sums only (no in-place write).
__global__ void scanA_kernel() {
    int c = blockIdx.x, b = blockIdx.y;
    int r = threadIdx.x;
    float ret = g_ret[b*Rr + r];
    const float* base = g_sig + ((size_t)(b*Ss + c*CLEN))*Rr + r;
    float a = 0.f;
    #pragma unroll 8
    for (int t = 0; t < CLEN; t++)
        a = fmaf(a, ret, base[(size_t)t*Rr]);
    g_carrySum[(size_t)(b*CHUNKS + c)*Rr + r] = a;
}
__global__ void scanB_kernel(const float* __restrict__ prev,
                             float* __restrict__ final_state) {
    int b = blockIdx.x, r = threadIdx.x;
    float ret = g_ret[b*Rr + r];
    float p = ret;
    #pragma unroll
    for (int i = 0; i < 6; i++) p *= p;   // ret^64
    float carry = prev[b*Rr + r];
    #pragma unroll 4
    for (int c = 0; c < CHUNKS; c++) {
        g_carryIn[(size_t)(b*CHUNKS + c)*Rr + r] = carry;
        carry = fmaf(carry, p, g_carrySum[(size_t)(b*CHUNKS + c)*Rr + r]);
    }
    final_state[b*Rr + r] = carry;
}
// scanC: full local scan + carry, emit bf16 hi/lo of accumulated.
__global__ void scanC_kernel() {
    int c = blockIdx.x, b = blockIdx.y;
    int r = threadIdx.x;
    float ret = g_ret[b*Rr + r];
    float cin = g_carryIn[(size_t)(b*CHUNKS + c)*Rr + r];
    float mlt = ret;
    float a = 0.f;
    size_t base = ((size_t)(b*Ss + c*CLEN))*Rr + r;
    #pragma unroll 8
    for (int t = 0; t < CLEN; t++) {
        a = fmaf(a, ret, g_sig[base + (size_t)t*Rr]);
        float v = fmaf(cin, mlt, a);
        unsigned short h, l;
        split1(v, h, l);
        ((unsigned short*)g_acc_hi)[base + (size_t)t*Rr] = h;
        ((unsigned short*)g_acc_lo)[base + (size_t)t*Rr] = l;
        mlt *= ret;
    }
}

// ---------------------------------------------------------------------------
#define GEMM_SMEM (3*65536)

extern "C" void kernel_launch(void* const* d_in, const int* in_sizes, int n_in,
                              void* d_out, int out_size) {
    const float* x     = (const float*)d_in[0];
    const float* prev  = (const float*)d_in[1];
    const float* freq  = (const float*)d_in[2];
    const float* rbias = (const float*)d_in[3];
    const float* rw    = (const float*)d_in[4];
    const float* gw    = (const float*)d_in[5];
    const float* gbias = (const float*)d_in[6];
    const float* outw  = (const float*)d_in[7];
    float* out = (float*)d_out;
    float* final_state = out + (size_t)Mtot*Dd;

    cudaFuncSetAttribute(gemm_hmma<16,true>,  cudaFuncAttributeMaxDynamicSharedMemorySize, GEMM_SMEM);
    cudaFuncSetAttribute(gemm_hmma<4,false>,  cudaFuncAttributeMaxDynamicSharedMemorySize, GEMM_SMEM);

    __nv_bfloat16 *xhi, *xlo, *fhi, *flo, *ohi, *olo, *ahi, *alo;
    cudaGetSymbolAddress((void**)&xhi, g_x_hi);
    cudaGetSymbolAddress((void**)&xlo, g_x_lo);
    cudaGetSymbolAddress((void**)&fhi, g_fnorm_hi);
    cudaGetSymbolAddress((void**)&flo, g_fnorm_lo);
    cudaGetSymbolAddress((void**)&ohi, g_outw_hi);
    cudaGetSymbolAddress((void**)&olo, g_outw_lo);
    cudaGetSymbolAddress((void**)&ahi, g_acc_hi);
    cudaGetSymbolAddress((void**)&alo, g_acc_lo);
    float* sig;
    cudaGetSymbolAddress((void**)&sig, g_sig);

    fnorm_kernel<<<Rr, 256>>>(freq);
    outw_split_kernel<<<256, 256>>>(outw);
    xprep_kernel<<<XBLKS, 256>>>(x);
    xm_reduce_kernel<<<Bb*4, 256>>>();
    gates_kernel<<<256, 256>>>(gw, gbias, rw, rbias);

    // GEMM1: sig = (x . fnorm^T) * invnorm[m] * gate[b,r]
    gemm_hmma<16,true><<<dim3(Rr/128, Mtot/128), 256, GEMM_SMEM>>>(
        xhi, xlo, fhi, flo, sig, Rr);

    scanA_kernel<<<dim3(CHUNKS, Bb), 256>>>();
    scanB_kernel<<<Bb, Rr>>>(prev, final_state);
    scanC_kernel<<<dim3(CHUNKS, Bb), 256>>>();

    // GEMM2: out = acc . out_w^T
    gemm_hmma<4,false><<<dim3(Dd/128, Mtot/128), 256, GEMM_SMEM>>>(
        ahi, alo, ohi, olo, out, Dd);
}